// round 16
// baseline (speedup 1.0000x reference)
#include <cuda_runtime.h>
#include <mma.h>
#include <math.h>
#include <stdint.h>

#define NROWS 8192
#define DIM 512

__device__ float g_Q [NROWS*DIM];
__device__ float g_K [NROWS*DIM];
__device__ float g_V [NROWS*DIM];
__device__ float g_XR[NROWS*DIM];
__device__ float g_H [NROWS*DIM];
__device__ float g_XP[NROWS*DIM];
__device__ float g_W2q[DIM*DIM];
__device__ float g_W2k[DIM*DIM];
__device__ float g_W2v[DIM*DIM];
__device__ float g_W2f[DIM*DIM];
__device__ float g_W2p[DIM*DIM];

__device__ __forceinline__ float tf32r(float v) { return nvcuda::wmma::__float_to_tf32(v); }

__device__ __forceinline__ void mma8(float* c, const float* a, const float* b) {
    asm volatile("mma.sync.aligned.m16n8k8.row.col.f32.tf32.tf32.f32 "
        "{%0,%1,%2,%3}, {%4,%5,%6,%7}, {%8,%9}, {%0,%1,%2,%3};"
        : "+f"(c[0]), "+f"(c[1]), "+f"(c[2]), "+f"(c[3])
        : "r"(__float_as_uint(a[0])), "r"(__float_as_uint(a[1])),
          "r"(__float_as_uint(a[2])), "r"(__float_as_uint(a[3])),
          "r"(__float_as_uint(b[0])), "r"(__float_as_uint(b[1])));
}

__device__ __forceinline__ void cpa16(uint32_t dst, const void* src) {
    asm volatile("cp.async.cg.shared.global [%0], [%1], 16;" :: "r"(dst), "l"(src));
}
#define CPA_COMMIT() asm volatile("cp.async.commit_group;" ::: "memory")
#define CPA_WAIT0()  asm volatile("cp.async.wait_group 0;"  ::: "memory")
#define CPA_WAIT1()  asm volatile("cp.async.wait_group 1;"  ::: "memory")
#define CPA_WAIT2()  asm volatile("cp.async.wait_group 2;"  ::: "memory")

// ===========================================================================
// Prep: xP = tf32-rounded x with PERM1 columns (pair-interleave in 8-groups).
// W'' = tf32-rounded weights in V''-form: (k,n) -> (k>>3)*4096 + n*8 + pp(k&7).
// ===========================================================================
__global__ void prep_x(const float* __restrict__ x, float* __restrict__ xP)
{
    int idx = blockIdx.x * 256 + threadIdx.x;       // 1M float4s
    int m = idx >> 7, c4 = (idx & 127) * 4;
    float4 v = *(const float4*)&x[(size_t)m*DIM + c4];
    float* base = xP + (size_t)m*DIM + (c4 & ~7);
    int off = (c4 & 4) ? 1 : 0;
    base[off]     = tf32r(v.x);
    base[off + 2] = tf32r(v.y);
    base[off + 4] = tf32r(v.z);
    base[off + 6] = tf32r(v.w);
}

__global__ void prep_w(
    const float* __restrict__ Wq, const float* __restrict__ Wk,
    const float* __restrict__ Wv, const float* __restrict__ Wf,
    const float* __restrict__ Wp,
    float* __restrict__ W2q, float* __restrict__ W2k, float* __restrict__ W2v,
    float* __restrict__ W2f, float* __restrict__ W2p)
{
    int seg = blockIdx.y;
    const float* W = seg == 0 ? Wq : seg == 1 ? Wk : seg == 2 ? Wv
                   : seg == 3 ? Wf : Wp;
    float* W2      = seg == 0 ? W2q : seg == 1 ? W2k : seg == 2 ? W2v
                   : seg == 3 ? W2f : W2p;
    int idx = blockIdx.x * 256 + threadIdx.x;       // 65536 float4s
    int k = idx >> 7, c4 = (idx & 127) * 4;
    float4 v = *(const float4*)&W[(size_t)k*DIM + c4];
    int k7 = k & 7;
    int pk = (k7 < 4) ? 2*k7 : 2*(k7-4)+1;
    float* o = W2 + (size_t)(k >> 3)*4096 + pk;
    o[(size_t)(c4+0)*8] = tf32r(v.x);
    o[(size_t)(c4+1)*8] = tf32r(v.y);
    o[(size_t)(c4+2)*8] = tf32r(v.z);
    o[(size_t)(c4+3)*8] = tf32r(v.w);
}

// ===========================================================================
// Retention (round-15 proven core).  Epilogue now writes XR PERM1 + rounded.
// ===========================================================================
#define STG_FL   12800
#define RING_FL  38400
#define REG2_FL  16640
#define SSP_FL   16896
#define RET_SMEM ((RING_FL + REG2_FL) * 4)

__global__ void __launch_bounds__(512, 1) retention_mma(
    const float* __restrict__ Q, const float* __restrict__ K,
    const float* __restrict__ V, const float* __restrict__ D,
    float* __restrict__ O)
{
    extern __shared__ float sm[];
    float* Ssp = sm;

    const int tid = threadIdx.x;
    const int lane = tid & 31, w = tid >> 5;
    const int wm = w >> 3, wn = w & 7;
    const int qr = lane >> 2, qc = lane & 3;
    const int i0 = blockIdx.x * 64;

    const uint32_t sBase = (uint32_t)__cvta_generic_to_shared(sm);
    const uint32_t slotB = (uint32_t)STG_FL * 4u;

    const int l_r = tid >> 3, l_c = (tid & 7) * 4;
    const uint32_t qSm = (uint32_t)(l_r*40 + l_c) * 4u;
    const uint32_t kSm = qSm + 2560u*4u;
    const int ld_r = tid >> 6, ld_c = (tid & 63) * 4;
    const uint32_t dSm0 = sBase + (uint32_t)RING_FL*4u
                        + (uint32_t)(ld_r*260 + ld_c)*4u;
    const uint32_t vSm = (uint32_t)tid * 16u;

    const float* Qg = Q + (size_t)(i0 + l_r)*DIM + l_c;

    const int aQ  = (wm*32 + qr)*40 + 2*qc;
    const int bK  = 2560 + (wn*32 + qr)*40 + 2*qc;
    const int dR  = (wm*32 + qr)*260 + wn*32 + 2*qc;
    const int spos = ((2*qc) & 3) * 2 + (qc >> 1);
    const int sW  = (wm*32 + qr)*264 + wn*32 + spos;
    const int sA  = (wm*32 + qr)*264 + 2*qc;
    const int vB  = (wn*64 + qr)*8 + 2*qc;

    float o[2][8][4];
    #pragma unroll
    for (int f = 0; f < 2; f++)
        #pragma unroll
        for (int g = 0; g < 8; g++)
            #pragma unroll
            for (int e = 0; e < 4; e++) o[f][g][e] = 0.f;

    #pragma unroll 1
    for (int j0 = 0; j0 < NROWS; j0 += 256) {
        const float* qq = Qg;
        const float* kk = K + (size_t)(j0 + l_r)*DIM + l_c;
        const float* dd = D + (size_t)(i0 + ld_r)*NROWS + j0 + ld_c;
        uint32_t bI = sBase;
        uint32_t dI = dSm0;

        auto issue_qk = [&]() {
            cpa16(bI + qSm, qq);
            cpa16(bI + kSm,           kk);
            cpa16(bI + kSm + 10240u,  kk + 64*DIM);
            cpa16(bI + kSm + 20480u,  kk + 128*DIM);
            cpa16(bI + kSm + 30720u,  kk + 192*DIM);
            if (tid < 256) cpa16(dI, dd);
            CPA_COMMIT();
            qq += 32; kk += 32; dd += 4*NROWS; dI += 4160u;
            bI += slotB; if (bI == sBase + 3u*slotB) bI = sBase;
        };

        issue_qk();
        issue_qk();

        float s[2][4][4];
        #pragma unroll
        for (int f = 0; f < 2; f++)
            #pragma unroll
            for (int g = 0; g < 4; g++)
                #pragma unroll
                for (int e = 0; e < 4; e++) s[f][g][e] = 0.f;

        const float* Su = sm;
        #pragma unroll 1
        for (int kc = 0; kc < 16; kc++) {
            if (kc < 15) { CPA_WAIT1(); } else { CPA_WAIT0(); }
            __syncthreads();
            if (kc < 14) issue_qk();
            const float* Qa = Su + aQ;
            const float* Kb = Su + bK;
            #pragma unroll
            for (int k8 = 0; k8 < 4; k8++) {
                const int kp = k8*8;
                float2 a00 = *(const float2*)(Qa + kp);
                float2 a01 = *(const float2*)(Qa + kp + 320);
                float2 a10 = *(const float2*)(Qa + kp + 640);
                float2 a11 = *(const float2*)(Qa + kp + 960);
                float a0[4] = { a00.x, a01.x, a00.y, a01.y };
                float a1[4] = { a10.x, a11.x, a10.y, a11.y };
                #pragma unroll
                for (int g = 0; g < 4; g++) {
                    float2 bb = *(const float2*)(Kb + kp + g*320);
                    float b[2] = { bb.x, bb.y };
                    mma8(s[0][g], a0, b);
                    mma8(s[1][g], a1, b);
                }
            }
            Su += STG_FL; if (Su == sm + 3*STG_FL) Su = sm;
        }
        __syncthreads();

        const float* vv = V + (size_t)j0 * DIM + tid*4;
        int vIss = 0;
        auto issue_v = [&]() {
            int i = vIss & 3;
            uint32_t b = sBase
                + (uint32_t)(((i & 2) ? RING_FL : SSP_FL) + (i & 1)*8192) * 4u
                + vSm;
            cpa16(b,          vv);
            cpa16(b + 8192u,  vv + 2048);
            cpa16(b + 16384u, vv + 4096);
            cpa16(b + 24576u, vv + 6144);
            CPA_COMMIT();
            vv += 8192; vIss++;
        };

        issue_v();
        issue_v();

        {
            const float* DsB = sm + RING_FL + dR;
            float* SspW = Ssp + sW;
            #pragma unroll
            for (int f = 0; f < 2; f++)
                #pragma unroll
                for (int g = 0; g < 4; g++) {
                    float2 d0 = *(const float2*)(DsB + f*4160 + g*8);
                    float2 d1 = *(const float2*)(DsB + f*4160 + g*8 + 2080);
                    float* wp = SspW + f*4224 + g*8;
                    wp[0]    = tf32r(s[f][g][0]*d0.x);
                    wp[2]    = tf32r(s[f][g][1]*d0.y);
                    wp[2112] = tf32r(s[f][g][2]*d1.x);
                    wp[2114] = tf32r(s[f][g][3]*d1.y);
                }
        }
        __syncthreads();

        issue_v();

        const float* SspA = Ssp + sA;
        #pragma unroll 1
        for (int st = 0; st < 16; st++) {
            if (st < 14) { CPA_WAIT2(); }
            else if (st < 15) { CPA_WAIT1(); }
            else { CPA_WAIT0(); }
            __syncthreads();
            if (st + 3 < 16) issue_v();
            const float* Vb = sm
                + (((st & 2) ? RING_FL : SSP_FL) + (st & 1)*8192) + vB;
            #pragma unroll
            for (int sub = 0; sub < 2; sub++) {
                const int G8 = (st*2 + sub)*8;
                float2 p00 = *(const float2*)(SspA + G8);
                float2 p01 = *(const float2*)(SspA + G8 + 2112);
                float2 p10 = *(const float2*)(SspA + G8 + 4224);
                float2 p11 = *(const float2*)(SspA + G8 + 6336);
                float a0[4] = { p00.x, p01.x, p00.y, p01.y };
                float a1[4] = { p10.x, p11.x, p10.y, p11.y };
                const float* vp = Vb + sub*4096;
                #pragma unroll
                for (int g = 0; g < 8; g++) {
                    float2 bb = *(const float2*)(vp + g*64);
                    float b[2] = { bb.x, bb.y };
                    mma8(o[0][g], a0, b);
                    mma8(o[1][g], a1, b);
                }
            }
        }
        __syncthreads();
    }

    // epilogue: XR in PERM1 + rounded (feeds Wf GEMM's cp.async A path)
    #pragma unroll
    for (int f = 0; f < 2; f++)
        #pragma unroll
        for (int g = 0; g < 8; g++) {
            int r = i0 + wm*32 + f*16 + qr;
            int c = wn*64 + g*8 + 2*qc;
            int m0 = c & 7, m1 = m0 + 1;
            int p0 = (c & ~7) + ((m0 < 4) ? 2*m0 : 2*(m0-4)+1);
            int p1 = (c & ~7) + ((m1 < 4) ? 2*m1 : 2*(m1-4)+1);
            O[(size_t)r*DIM + p0]       = tf32r(o[f][g][0]);
            O[(size_t)r*DIM + p1]       = tf32r(o[f][g][1]);
            O[(size_t)(r + 8)*DIM + p0] = tf32r(o[f][g][2]);
            O[(size_t)(r + 8)*DIM + p1] = tf32r(o[f][g][3]);
        }
}

// ===========================================================================
// Fast GEMM core: A (PERM1 columns, pre-rounded) x B'' (pre-rounded).
// BM=128, BN=64, BK=32, 256 thr, warps 4(m)x2(n), tile 32x32.
// 3-slot cp.async ring; no CVT/STS in the loop; all frags LDS.64.
// Stage: A 128x40 = 5120 fl | B'' 4x64x8 = 2048 fl -> 7168 fl; ring 21504 fl.
// ===========================================================================
#define GF_STG  7168
#define GF_SMEM (3*GF_STG*4)        // 86016 B

struct GFOut { float v[2][4][4]; };

__device__ __forceinline__ void gemm_core(
    const float* __restrict__ A, const float* __restrict__ W2,
    int bm, int bn, int tid, GFOut& out)
{
    extern __shared__ float sm[];
    const uint32_t sBase = (uint32_t)__cvta_generic_to_shared(sm);
    const int lane = tid & 31, w = tid >> 5;
    const int wm = w >> 1, wn = w & 1;
    const int qr = lane >> 2, qc = lane & 3;

    // loader constants
    const int la_r = tid >> 3, la_c = (tid & 7) * 4;   // A: 4 passes of 32 rows
    const int lb_kb = tid >> 7;                        // B: 2 passes
    const int lb_w  = (tid & 127) * 4;
    const uint32_t aSm = (uint32_t)(la_r*40 + la_c) * 4u;
    const uint32_t bSm = (uint32_t)(5120 + lb_kb*512 + lb_w) * 4u;

    const float* aP = A + (size_t)(bm + la_r)*DIM + la_c;
    const float* bP = W2 + (size_t)lb_kb*4096 + bn*8 + lb_w;
    uint32_t bI = sBase;

    auto issue = [&]() {
        cpa16(bI + aSm,            aP);
        cpa16(bI + aSm + 5120u,    aP + 32*DIM);
        cpa16(bI + aSm + 10240u,   aP + 64*DIM);
        cpa16(bI + aSm + 15360u,   aP + 96*DIM);
        cpa16(bI + bSm,            bP);
        cpa16(bI + bSm + 4096u,    bP + 2*4096);
        CPA_COMMIT();
        aP += 32; bP += 4*4096;
        bI += (uint32_t)GF_STG*4u;
        if (bI == sBase + 3u*GF_STG*4u) bI = sBase;
    };

    issue();
    issue();

    float acc[2][4][4];
    #pragma unroll
    for (int f = 0; f < 2; f++)
        #pragma unroll
        for (int g = 0; g < 4; g++)
            #pragma unroll
            for (int e = 0; e < 4; e++) acc[f][g][e] = 0.f;

    const int aO = (wm*32 + qr)*40 + 2*qc;
    const int bO = 5120 + (wn*32 + qr)*8 + 2*qc;

    const float* Su = sm;
    #pragma unroll 1
    for (int kt = 0; kt < 16; kt++) {
        if (kt < 15) { CPA_WAIT1(); } else { CPA_WAIT0(); }
        __syncthreads();
        if (kt < 14) issue();
        const float* Aa = Su + aO;
        const float* Bb = Su + bO;
        #pragma unroll
        for (int k8 = 0; k8 < 4; k8++) {
            float2 a00 = *(const float2*)(Aa + k8*8);
            float2 a01 = *(const float2*)(Aa + k8*8 + 320);
            float2 a10 = *(const float2*)(Aa + k8*8 + 640);
            float2 a11 = *(const float2*)(Aa + k8*8 + 960);
            float a0[4] = { a00.x, a01.x, a00.y, a01.y };
            float a1[4] = { a10.x, a11.x, a10.y, a11.y };
            const float* bk8 = Bb + k8*512;
            #pragma unroll
            for (int g = 0; g < 4; g++) {
                float2 bb = *(const float2*)(bk8 + g*64);
                float b[2] = { bb.x, bb.y };
                mma8(acc[0][g], a0, b);
                mma8(acc[1][g], a1, b);
            }
        }
        Su += GF_STG; if (Su == sm + 3*GF_STG) Su = sm;
    }

    #pragma unroll
    for (int f = 0; f < 2; f++)
        #pragma unroll
        for (int g = 0; g < 4; g++)
            #pragma unroll
            for (int e = 0; e < 4; e++) out.v[f][g][e] = acc[f][g][e];
}

// Consumer GEMM: ACT=1 exact GELU; GN=1 fused GroupNorm; OUTP=1 PERM1+round.
template<int ACT, int GN, int OUTP>
__global__ void __launch_bounds__(256) gemm_fast(
    const float* __restrict__ A, const float* __restrict__ W2,
    const float* __restrict__ bias,
    const float* __restrict__ gamma, const float* __restrict__ beta,
    float* __restrict__ C)
{
    const int tid = threadIdx.x;
    const int lane = tid & 31, w = tid >> 5;
    const int wm = w >> 1, wn = w & 1;
    const int qr = lane >> 2, qc = lane & 3;
    const int bm = blockIdx.x * 128, bn = blockIdx.y * 64;

    GFOut out;
    gemm_core(A, W2, bm, bn, tid, out);
    float (*acc)[4][4] = out.v;

    #pragma unroll
    for (int f = 0; f < 2; f++)
        #pragma unroll
        for (int g = 0; g < 4; g++) {
            int c = bn + wn*32 + g*8 + 2*qc;
            float2 bb = *(const float2*)&bias[c];
            acc[f][g][0] += bb.x; acc[f][g][1] += bb.y;
            acc[f][g][2] += bb.x; acc[f][g][3] += bb.y;
            if (ACT == 1) {
                #pragma unroll
                for (int e = 0; e < 4; e++) {
                    float v = acc[f][g][e];
                    acc[f][g][e] = 0.5f*v*(1.f + erff(v*0.70710678118654752f));
                }
            }
        }

    if (GN == 1) {
        #pragma unroll
        for (int f = 0; f < 2; f++) {
            float s0 = 0.f, q0 = 0.f, s1 = 0.f, q1 = 0.f;
            #pragma unroll
            for (int g = 0; g < 4; g++) {
                s0 += acc[f][g][0] + acc[f][g][1];
                q0 += acc[f][g][0]*acc[f][g][0] + acc[f][g][1]*acc[f][g][1];
                s1 += acc[f][g][2] + acc[f][g][3];
                q1 += acc[f][g][2]*acc[f][g][2] + acc[f][g][3]*acc[f][g][3];
            }
            #pragma unroll
            for (int off = 1; off <= 2; off <<= 1) {
                s0 += __shfl_xor_sync(0xffffffff, s0, off);
                q0 += __shfl_xor_sync(0xffffffff, q0, off);
                s1 += __shfl_xor_sync(0xffffffff, s1, off);
                q1 += __shfl_xor_sync(0xffffffff, q1, off);
            }
            float mu0 = s0*(1.f/32.f), iv0 = rsqrtf(q0*(1.f/32.f) - mu0*mu0 + 1e-5f);
            float mu1 = s1*(1.f/32.f), iv1 = rsqrtf(q1*(1.f/32.f) - mu1*mu1 + 1e-5f);
            #pragma unroll
            for (int g = 0; g < 4; g++) {
                int c = bn + wn*32 + g*8 + 2*qc;
                float2 gm = *(const float2*)&gamma[c];
                float2 bt = *(const float2*)&beta[c];
                acc[f][g][0] = (acc[f][g][0] - mu0)*iv0*gm.x + bt.x;
                acc[f][g][1] = (acc[f][g][1] - mu0)*iv0*gm.y + bt.y;
                acc[f][g][2] = (acc[f][g][2] - mu1)*iv1*gm.x + bt.x;
                acc[f][g][3] = (acc[f][g][3] - mu1)*iv1*gm.y + bt.y;
            }
        }
    }

    #pragma unroll
    for (int f = 0; f < 2; f++)
        #pragma unroll
        for (int g = 0; g < 4; g++) {
            int r = bm + wm*32 + f*16 + qr;
            int c = bn + wn*32 + g*8 + 2*qc;
            if (OUTP == 1) {
                int m0 = c & 7, m1 = m0 + 1;
                int p0 = (c & ~7) + ((m0 < 4) ? 2*m0 : 2*(m0-4)+1);
                int p1 = (c & ~7) + ((m1 < 4) ? 2*m1 : 2*(m1-4)+1);
                C[(size_t)r*DIM + p0]       = tf32r(acc[f][g][0]);
                C[(size_t)r*DIM + p1]       = tf32r(acc[f][g][1]);
                C[(size_t)(r + 8)*DIM + p0] = tf32r(acc[f][g][2]);
                C[(size_t)(r + 8)*DIM + p1] = tf32r(acc[f][g][3]);
            } else {
                *(float2*)&C[(size_t)r*DIM + c] =
                    make_float2(acc[f][g][0], acc[f][g][1]);
                *(float2*)&C[(size_t)(r + 8)*DIM + c] =
                    make_float2(acc[f][g][2], acc[f][g][3]);
            }
        }
}

// Merged Q/K/V producer: seg = by>>3 (0:Q,1:K paired; 2:V'').  A = xP.
__global__ void __launch_bounds__(256) gemm_qkv(
    const float* __restrict__ A,
    const float* __restrict__ W2q, const float* __restrict__ bq, float* __restrict__ Qo,
    const float* __restrict__ W2k, const float* __restrict__ bk, float* __restrict__ Ko,
    const float* __restrict__ W2v, const float* __restrict__ bv, float* __restrict__ Vo)
{
    const int seg = blockIdx.y >> 3;
    const float* W2   = seg == 0 ? W2q : (seg == 1 ? W2k : W2v);
    const float* bias = seg == 0 ? bq  : (seg == 1 ? bk  : bv);
    float* C          = seg == 0 ? Qo  : (seg == 1 ? Ko  : Vo);
    const int bn = (blockIdx.y & 7) * 64;
    const int bm = blockIdx.x * 128;

    const int tid = threadIdx.x;
    const int lane = tid & 31, w = tid >> 5;
    const int wm = w >> 1, wn = w & 1;
    const int qr = lane >> 2, qc = lane & 3;

    GFOut out;
    gemm_core(A, W2, bm, bn, tid, out);
    float (*acc)[4][4] = out.v;

    #pragma unroll
    for (int f = 0; f < 2; f++)
        #pragma unroll
        for (int g = 0; g < 4; g++) {
            int r = bm + wm*32 + f*16 + qr;
            int c = bn + wn*32 + g*8 + 2*qc;
            float2 bb = *(const float2*)&bias[c];
            float v0 = tf32r(acc[f][g][0] + bb.x);
            float v1 = tf32r(acc[f][g][1] + bb.y);
            float v2 = tf32r(acc[f][g][2] + bb.x);
            float v3 = tf32r(acc[f][g][3] + bb.y);
            if (seg < 2) {
                int m0 = c & 7, m1 = m0 + 1;
                int p0 = (c & ~7) + ((m0 < 4) ? 2*m0 : 2*(m0-4)+1);
                int p1 = (c & ~7) + ((m1 < 4) ? 2*m1 : 2*(m1-4)+1);
                C[(size_t)r*DIM + p0]       = v0;
                C[(size_t)r*DIM + p1]       = v1;
                C[(size_t)(r + 8)*DIM + p0] = v2;
                C[(size_t)(r + 8)*DIM + p1] = v3;
            } else {
                int ppr = (qr < 4) ? 2*qr : 2*(qr-4)+1;
                size_t a0 = (size_t)(r >> 3)*4096 + (size_t)c*8 + ppr;
                C[a0]        = v0;
                C[a0 + 8]    = v1;
                C[a0 + 4096] = v2;
                C[a0 + 4104] = v3;
            }
        }
}

// ---------------------------------------------------------------------------
extern "C" void kernel_launch(void* const* d_in, const int* in_sizes, int n_in,
                              void* d_out, int out_size)
{
    const float* x     = (const float*)d_in[0];
    const float* D     = (const float*)d_in[1];
    const float* Wq    = (const float*)d_in[2];
    const float* bq    = (const float*)d_in[3];
    const float* Wk    = (const float*)d_in[4];
    const float* bk    = (const float*)d_in[5];
    const float* Wv    = (const float*)d_in[6];
    const float* bv    = (const float*)d_in[7];
    const float* Wf    = (const float*)d_in[8];
    const float* bf    = (const float*)d_in[9];
    const float* Wp    = (const float*)d_in[10];
    const float* bp    = (const float*)d_in[11];
    const float* gamma = (const float*)d_in[12];
    const float* beta  = (const float*)d_in[13];
    float* out = (float*)d_out;

    float *Q, *K, *V, *XR, *H, *XP, *W2q, *W2k, *W2v, *W2f, *W2p;
    cudaGetSymbolAddress((void**)&Q,   g_Q);
    cudaGetSymbolAddress((void**)&K,   g_K);
    cudaGetSymbolAddress((void**)&V,   g_V);
    cudaGetSymbolAddress((void**)&XR,  g_XR);
    cudaGetSymbolAddress((void**)&H,   g_H);
    cudaGetSymbolAddress((void**)&XP,  g_XP);
    cudaGetSymbolAddress((void**)&W2q, g_W2q);
    cudaGetSymbolAddress((void**)&W2k, g_W2k);
    cudaGetSymbolAddress((void**)&W2v, g_W2v);
    cudaGetSymbolAddress((void**)&W2f, g_W2f);
    cudaGetSymbolAddress((void**)&W2p, g_W2p);

    cudaFuncSetAttribute(gemm_qkv,
                         cudaFuncAttributeMaxDynamicSharedMemorySize, GF_SMEM);
    cudaFuncSetAttribute(gemm_fast<1,0,1>,
                         cudaFuncAttributeMaxDynamicSharedMemorySize, GF_SMEM);
    cudaFuncSetAttribute(gemm_fast<0,1,0>,
                         cudaFuncAttributeMaxDynamicSharedMemorySize, GF_SMEM);
    cudaFuncSetAttribute(retention_mma,
                         cudaFuncAttributeMaxDynamicSharedMemorySize, RET_SMEM);

    prep_x<<<4096, 256>>>(x, XP);
    prep_w<<<dim3(256, 5), 256>>>(Wq, Wk, Wv, Wf, Wp,
                                  W2q, W2k, W2v, W2f, W2p);

    gemm_qkv<<<dim3(NROWS/128, 24), 256, GF_SMEM>>>(
        XP, W2q, bq, Q, W2k, bk, K, W2v, bv, V);

    retention_mma<<<NROWS/64, 512, RET_SMEM>>>(Q, K, V, D, XR);

    dim3 gs(NROWS/128, DIM/64);
    gemm_fast<1,0,1><<<gs, 256, GF_SMEM>>>(XR, W2f, bf, 0, 0, H);
    gemm_fast<0,1,0><<<gs, 256, GF_SMEM>>>(H, W2p, bp, gamma, beta, out);
}